// round 8
// baseline (speedup 1.0000x reference)
#include <cuda_runtime.h>
#include <cstdint>

#define SQRT2F     1.4142135623730951f
#define INVSQRT2F  0.7071067811865476f

using u32 = uint32_t; using u64 = uint64_t; using ull = unsigned long long;

// ======================= helpers =======================
__device__ __forceinline__ ull pack2(float lo, float hi) {
    ull r; asm("mov.b64 %0, {%1, %2};" : "=l"(r) : "f"(lo), "f"(hi)); return r;
}
__device__ __forceinline__ void unpack2(ull v, float& lo, float& hi) {
    asm("mov.b64 {%0, %1}, %2;" : "=f"(lo), "=f"(hi) : "l"(v));
}
__device__ __forceinline__ void fma2(ull& d, ull a, ull b) {
    asm("fma.rn.f32x2 %0, %1, %2, %0;" : "+l"(d) : "l"(a), "l"(b));
}
__device__ __forceinline__ u32 f2tf32(float f) {
    u32 r; asm("cvt.rna.tf32.f32 %0, %1;" : "=r"(r) : "f"(f)); return r;
}
__device__ __forceinline__ u32 smem_u32(const void* p) {
    u32 a; asm("{ .reg .u64 t; cvta.to.shared.u64 t, %1; cvt.u32.u64 %0, t; }" : "=r"(a) : "l"(p));
    return a;
}
__device__ __forceinline__ void cp4(u32 dst, const void* src) {
    asm volatile("cp.async.ca.shared.global [%0], [%1], 4;" :: "r"(dst), "l"(src));
}
__device__ __forceinline__ void cp16(u32 dst, const void* src) {
    asm volatile("cp.async.ca.shared.global [%0], [%1], 16;" :: "r"(dst), "l"(src));
}
#define CP_COMMIT() asm volatile("cp.async.commit_group;" ::: "memory")
#define CP_WAIT(N)  asm volatile("cp.async.wait_group %0;" :: "n"(N) : "memory")

__device__ __forceinline__ void mma_tf32(float* c, const u32* a, const u32* b) {
    asm volatile("mma.sync.aligned.m16n8k8.row.col.f32.tf32.tf32.f32 "
                 "{%0,%1,%2,%3}, {%4,%5,%6,%7}, {%8,%9}, {%0,%1,%2,%3};"
                 : "+f"(c[0]), "+f"(c[1]), "+f"(c[2]), "+f"(c[3])
                 : "r"(a[0]), "r"(a[1]), "r"(a[2]), "r"(a[3]),
                   "r"(b[0]), "r"(b[1]));
}

// ======================= scratch =======================
__device__ __align__(16) float g_p1[8 * 256 * 66 * 66];        // padded conv1 input, tf32-rounded
__device__ __align__(16) float g_out1[8 * 256 * 64 * 64];      // conv1 output (after lrelu, fp32)
__device__ __align__(16) float g_up_pad[8 * 256 * 130 * 130];  // padded upsampled, tf32-rounded
__device__ __align__(16) float g_s64[8 * 128 * 64 * 64];       // 1x1 skip conv at 64x64 (fp32)
__device__ __align__(16) u32   g_wB1[2 * 72 * 4096];           // conv1 wts tf32 [cot][chunk][k=32][co=128]
__device__ __align__(16) u32   g_wB2[72 * 4096];               // conv2 wts tf32 [chunk][k=32][co=128]
__device__ __align__(16) float g_wskT[256 * 128];              // skip weights [ci][co], scaled

// ======================= weight prep =======================
__global__ void k_wt1(const float* __restrict__ w) {
    int idx = blockIdx.x * 256 + threadIdx.x;        // 2*72*32*128 = 589824
    if (idx >= 589824) return;
    int co_l  = idx & 127;
    int k_l   = (idx >> 7) & 31;
    int chunk = idx >> 12;                            // 0..143
    int cot = chunk / 72, i = chunk % 72;
    int koff = i >> 3, cic = i & 7;
    int co = cot * 128 + co_l;
    int ci = cic * 32 + k_l;
    g_wB1[idx] = f2tf32(w[(co * 256 + ci) * 9 + koff] * (1.0f / 48.0f));
}
__global__ void k_wt2(const float* __restrict__ w) {
    int idx = blockIdx.x * 256 + threadIdx.x;        // 72*32*128 = 294912
    if (idx >= 294912) return;
    int co_l = idx & 127;
    int k_l  = (idx >> 7) & 31;
    int i    = idx >> 12;                             // 0..71
    int koff = i >> 3, cic = i & 7;
    int ci = cic * 32 + k_l;
    g_wB2[idx] = f2tf32(w[(co_l * 256 + ci) * 9 + koff] * (1.0f / 48.0f));
}
__global__ void k_wts(const float* __restrict__ w) {
    int idx = blockIdx.x * 256 + threadIdx.x;
    if (idx >= 256 * 128) return;
    int co = idx & 127; int ci = idx >> 7;
    g_wskT[idx] = w[co * 256 + ci] * (1.0f / 16.0f);
}

// ======================= pad x into g_p1 (tf32-rounded) =======================
__global__ void k_pad1(const float* __restrict__ x) {
    int idx = blockIdx.x * 256 + threadIdx.x;        // 8*256*64*64
    int c = idx & 63, r = (idx >> 6) & 63, nc = idx >> 12;
    g_p1[(size_t)nc * 4356 + (r + 1) * 66 + (c + 1)] = __uint_as_float(f2tf32(x[idx]));
}

// ======================= mma.sync tf32 implicit-GEMM conv (3x3, pad 1) =================
// cp.async double-buffered A & B tiles; dynamic smem = 2*(32*136)*2 u32 = 69632 B.
// CONV=1: in=g_p1 (66x66 pad), out 64x64, M-tile = 2 rows x 64 cols, cot {0,1} -> g_out1
// CONV=2: in=g_up_pad (130x130 pad), out 128x128, M-tile = 1 row x 128 cols -> d_out (+ fused skip)
template <int CONV>
__global__ void __launch_bounds__(256, 2) k_conv_mma(const float* __restrict__ bias,
                                                     float* __restrict__ dout) {
    constexpr int PW  = (CONV == 1) ? 66 : 130;
    constexpr int PSZ = PW * PW;
    constexpr int OW  = (CONV == 1) ? 64 : 128;
    constexpr int ROWS = 128 / OW;
    constexpr int TILE_U32 = 32 * 136;               // one stage, one matrix

    extern __shared__ __align__(16) u32 dynsmem[];
    u32* sA_s[2] = { dynsmem,                dynsmem + TILE_U32 };
    u32* sB_s[2] = { dynsmem + 2 * TILE_U32, dynsmem + 3 * TILE_U32 };
    const u32 sbase = smem_u32(dynsmem);

    const int tile = blockIdx.x;
    const int cot  = blockIdx.y;
    const int n    = blockIdx.z;
    const int tid  = threadIdx.x;
    const int wid  = tid >> 5;
    const int lane = tid & 31;
    const int warp_m = wid >> 1;       // 0..3
    const int warp_n = wid & 1;        // 0..1
    const int lg = lane >> 2;          // 0..7
    const int lt = lane & 3;           // 0..3

    const float* in = (CONV == 1) ? g_p1 : g_up_pad;
    const u32* wB = ((CONV == 1) ? g_wB1 + cot * 72 * 4096 : g_wB2);

    const int r0 = tile * ROWS;

    // A-load mapping: thread -> (k=ci within chunk, 16-px group)
    const int ak   = tid >> 3;                       // 0..31
    const int apx0 = (tid & 7) * 16;                 // 0,16,...,112
    const int arl  = (CONV == 1) ? (apx0 >> 6) : 0;  // row-within-tile
    const int ac   = apx0 & (OW - 1);
    const float* a_base = in + ((size_t)(n * 256 + ak)) * PSZ + (size_t)(r0 + arl) * PW + ac;

    auto load_tile = [&](int i, int st) {
        const int koff = i >> 3, cic = i & 7;
        const int ky = koff / 3, kx = koff - ky * 3;
        // B: 16KB, 4 x 16B per thread
        {
            const u32* src = wB + i * 4096;
            u32 dstb = sbase + (u32)((sB_s[st] - dynsmem) << 2);
#pragma unroll
            for (int p = 0; p < 4; p++) {
                int lin = (p * 256 + tid) << 2;          // u32 index, mult of 4
                int row = lin >> 7, col = lin & 127;
                cp16(dstb + (u32)((row * 136 + col) << 2), src + lin);
            }
        }
        // A: 16KB, 16 x 4B per thread (row = ci, 16 consecutive px)
        {
            const float* src = a_base + (size_t)(cic * 32) * PSZ + ky * PW + kx;
            u32 dsta = sbase + (u32)((sA_s[st] - dynsmem) << 2) + (u32)((ak * 136 + apx0) << 2);
#pragma unroll
            for (int j = 0; j < 16; j++) cp4(dsta + 4 * j, src + j);
        }
        CP_COMMIT();
    };

    float acc[2][8][4];
#pragma unroll
    for (int mt = 0; mt < 2; mt++)
#pragma unroll
        for (int nt = 0; nt < 8; nt++)
#pragma unroll
            for (int q = 0; q < 4; q++) acc[mt][nt][q] = 0.0f;

    load_tile(0, 0);

    for (int i = 0; i < 72; i++) {
        const int st = i & 1;
        if (i + 1 < 72) { load_tile(i + 1, st ^ 1); CP_WAIT(1); }
        else            { CP_WAIT(0); }
        __syncthreads();

        const u32* sA = sA_s[st];
        const u32* sB = sB_s[st];
#pragma unroll
        for (int ks = 0; ks < 4; ks++) {
            const int kc = ks * 8 + lt;
            const int rb = warp_m * 32 + lg;
            u32 a[2][4];
#pragma unroll
            for (int mt = 0; mt < 2; mt++) {
                a[mt][0] = sA[kc * 136 + rb + mt * 16];
                a[mt][1] = sA[kc * 136 + rb + mt * 16 + 8];
                a[mt][2] = sA[(kc + 4) * 136 + rb + mt * 16];
                a[mt][3] = sA[(kc + 4) * 136 + rb + mt * 16 + 8];
            }
            const int nb = warp_n * 64 + lg;
            u32 b[8][2];
#pragma unroll
            for (int nt = 0; nt < 8; nt++) {
                b[nt][0] = sB[kc * 136 + nb + nt * 8];
                b[nt][1] = sB[(kc + 4) * 136 + nb + nt * 8];
            }
#pragma unroll
            for (int mt = 0; mt < 2; mt++)
#pragma unroll
                for (int nt = 0; nt < 8; nt++)
                    mma_tf32(acc[mt][nt], a[mt], b[nt]);
        }
        __syncthreads();
    }

    // ---- epilogue ----
    if (CONV == 1) {
#pragma unroll
        for (int mt = 0; mt < 2; mt++) {
            const int p0 = warp_m * 32 + mt * 16 + lg;
            const int p1 = p0 + 8;
            const int or0 = r0 + (p0 >> 6), oc0 = p0 & 63;
            const int or1 = r0 + (p1 >> 6), oc1 = p1 & 63;
#pragma unroll
            for (int nt = 0; nt < 8; nt++) {
                const int co = cot * 128 + warp_n * 64 + nt * 8 + lt * 2;
                const float bv0 = bias[co], bv1 = bias[co + 1];
                float v00 = acc[mt][nt][0] + bv0;  v00 = (v00 >= 0.0f ? v00 : 0.2f * v00) * SQRT2F;
                float v01 = acc[mt][nt][1] + bv1;  v01 = (v01 >= 0.0f ? v01 : 0.2f * v01) * SQRT2F;
                float v10 = acc[mt][nt][2] + bv0;  v10 = (v10 >= 0.0f ? v10 : 0.2f * v10) * SQRT2F;
                float v11 = acc[mt][nt][3] + bv1;  v11 = (v11 >= 0.0f ? v11 : 0.2f * v11) * SQRT2F;
                g_out1[((size_t)(n * 256 + co)     << 12) + (or0 << 6) + oc0] = v00;
                g_out1[((size_t)(n * 256 + co + 1) << 12) + (or0 << 6) + oc0] = v01;
                g_out1[((size_t)(n * 256 + co)     << 12) + (or1 << 6) + oc1] = v10;
                g_out1[((size_t)(n * 256 + co + 1) << 12) + (or1 << 6) + oc1] = v11;
            }
        }
    } else {
        // fused: out = (conv2_act + bilinear_up(g_s64)) / sqrt(2); row u = r0 fixed.
        const int u = r0;
        int rr0, rr1; float wr0, wr1;
        { int iu = u >> 1;
          if (u & 1) { rr0 = iu; rr1 = min(iu + 1, 63); wr0 = 0.75f; wr1 = 0.25f; }
          else       { rr0 = max(iu - 1, 0); rr1 = iu;  wr0 = 0.25f; wr1 = 0.75f; } }
#pragma unroll
        for (int mt = 0; mt < 2; mt++) {
#pragma unroll
            for (int half = 0; half < 2; half++) {
                const int p  = warp_m * 32 + mt * 16 + half * 8 + lg;  // output col v
                int cc0, cc1; float wc0, wc1;
                { int jv = p >> 1;
                  if (p & 1) { cc0 = jv; cc1 = min(jv + 1, 63); wc0 = 0.75f; wc1 = 0.25f; }
                  else       { cc0 = max(jv - 1, 0); cc1 = jv;  wc0 = 0.25f; wc1 = 0.75f; } }
                const int i00 = (rr0 << 6) + cc0, i01 = (rr0 << 6) + cc1;
                const int i10 = (rr1 << 6) + cc0, i11 = (rr1 << 6) + cc1;
#pragma unroll
                for (int nt = 0; nt < 8; nt++) {
                    const int co = warp_n * 64 + nt * 8 + lt * 2;
                    const float bv0 = bias[co], bv1 = bias[co + 1];
                    float va = acc[mt][nt][half * 2 + 0] + bv0;
                    va = (va >= 0.0f ? va : 0.2f * va) * SQRT2F;
                    float vb = acc[mt][nt][half * 2 + 1] + bv1;
                    vb = (vb >= 0.0f ? vb : 0.2f * vb) * SQRT2F;
                    const float* s0 = g_s64 + ((size_t)(n * 128 + co) << 12);
                    const float* s1 = s0 + 4096;
                    float sk0 = wr0 * (wc0 * s0[i00] + wc1 * s0[i01])
                              + wr1 * (wc0 * s0[i10] + wc1 * s0[i11]);
                    float sk1 = wr0 * (wc0 * s1[i00] + wc1 * s1[i01])
                              + wr1 * (wc0 * s1[i10] + wc1 * s1[i11]);
                    dout[((size_t)(n * 128 + co)     << 14) + (u << 7) + p] = (va + sk0) * INVSQRT2F;
                    dout[((size_t)(n * 128 + co + 1) << 14) + (u << 7) + p] = (vb + sk1) * INVSQRT2F;
                }
            }
        }
    }
}

// ======================= bilinear 2x upsample (half-pixel, edge clamp) =================
__global__ void k_up256() {   // g_out1[.,.,64,64] -> g_up_pad interior [130x130], tf32-rounded
    int idx = blockIdx.x * 256 + threadIdx.x;
    int v = idx & 127, u = (idx >> 7) & 127, nc = idx >> 14;
    int i = u >> 1, j = v >> 1;
    int r0, r1, c0, c1; float wr0, wr1, wc0, wc1;
    if (u & 1) { r0 = i; r1 = min(i + 1, 63); wr0 = 0.75f; wr1 = 0.25f; }
    else       { r0 = max(i - 1, 0); r1 = i;  wr0 = 0.25f; wr1 = 0.75f; }
    if (v & 1) { c0 = j; c1 = min(j + 1, 63); wc0 = 0.75f; wc1 = 0.25f; }
    else       { c0 = max(j - 1, 0); c1 = j;  wc0 = 0.25f; wc1 = 0.75f; }
    const float* b = g_out1 + ((size_t)nc << 12);
    float val = wr0 * (wc0 * b[(r0 << 6) + c0] + wc1 * b[(r0 << 6) + c1])
              + wr1 * (wc0 * b[(r1 << 6) + c0] + wc1 * b[(r1 << 6) + c1]);
    g_up_pad[(size_t)nc * 16900 + (u + 1) * 130 + (v + 1)] = __uint_as_float(f2tf32(val));
}

// ======================= skip 1x1 conv at 64x64 (256->128), fp32 f32x2 =================
__global__ void __launch_bounds__(256) k_skip(const float* __restrict__ x) {
    const int n = blockIdx.z, cot = blockIdx.y;
    const int px0 = blockIdx.x * 64;
    const int tid = threadIdx.x;
    const int co_sub = tid >> 4, pxg = tid & 15;
    const int cobase = co_sub * 4, pxb = pxg * 4;
    __shared__ __align__(16) float s_x[16][64];
    __shared__ __align__(16) float s_w[16][64];
    ull acc[2][4];
#pragma unroll
    for (int p = 0; p < 2; p++)
#pragma unroll
        for (int j = 0; j < 4; j++) acc[p][j] = 0ull;

    for (int ci0 = 0; ci0 < 256; ci0 += 16) {
        __syncthreads();
        for (int i = tid; i < 1024; i += 256) {
            int ci_l = i >> 6, p = i & 63;
            s_x[ci_l][p] = x[((n * 256 + ci0 + ci_l) << 12) + px0 + p];
            s_w[ci_l][p] = g_wskT[(ci0 + ci_l) * 128 + cot * 64 + p];
        }
        __syncthreads();
#pragma unroll 4
        for (int ci = 0; ci < 16; ci++) {
            ull w0 = *(const ull*)&s_w[ci][cobase];
            ull w1 = *(const ull*)&s_w[ci][cobase + 2];
#pragma unroll
            for (int j = 0; j < 4; j++) {
                float v = s_x[ci][pxb + j];
                ull vb = pack2(v, v);
                fma2(acc[0][j], vb, w0);
                fma2(acc[1][j], vb, w1);
            }
        }
    }
#pragma unroll
    for (int p = 0; p < 2; p++) {
        int co = cot * 64 + cobase + 2 * p;
#pragma unroll
        for (int j = 0; j < 4; j++) {
            float lo, hi; unpack2(acc[p][j], lo, hi);
            g_s64[((n * 128 + co)     << 12) + px0 + pxb + j] = lo;
            g_s64[((n * 128 + co + 1) << 12) + px0 + pxb + j] = hi;
        }
    }
}

// ======================= launch =======================
extern "C" void kernel_launch(void* const* d_in, const int* in_sizes, int n_in,
                              void* d_out, int out_size) {
    const float* x   = (const float*)d_in[0];
    const float* w1  = (const float*)d_in[1];
    const float* b1  = (const float*)d_in[2];
    const float* w2  = (const float*)d_in[3];
    const float* b2  = (const float*)d_in[4];
    const float* wsk = (const float*)d_in[5];
    float* out = (float*)d_out;

    static const int SMEM_CONV = 4 * 32 * 136 * 4;   // 69632 B
    cudaFuncSetAttribute(k_conv_mma<1>, cudaFuncAttributeMaxDynamicSharedMemorySize, SMEM_CONV);
    cudaFuncSetAttribute(k_conv_mma<2>, cudaFuncAttributeMaxDynamicSharedMemorySize, SMEM_CONV);

    k_wt1<<<2304, 256>>>(w1);
    k_wt2<<<1152, 256>>>(w2);
    k_wts<<<128, 256>>>(wsk);
    k_pad1<<<32768, 256>>>(x);

    k_conv_mma<1><<<dim3(32, 2, 8), 256, SMEM_CONV>>>(b1, nullptr);
    k_up256<<<131072, 256>>>();                            // -> padded g_up_pad (tf32)
    k_skip<<<dim3(64, 2, 8), 256>>>(x);
    k_conv_mma<2><<<dim3(128, 1, 8), 256, SMEM_CONV>>>(b2, out);  // conv2 + fused skip
}

// round 9
// speedup vs baseline: 1.7930x; 1.7930x over previous
#include <cuda_runtime.h>
#include <cstdint>

#define SQRT2F     1.4142135623730951f
#define INVSQRT2F  0.7071067811865476f

using u32 = uint32_t; using u64 = uint64_t; using ull = unsigned long long;

// ======================= helpers =======================
__device__ __forceinline__ ull pack2(float lo, float hi) {
    ull r; asm("mov.b64 %0, {%1, %2};" : "=l"(r) : "f"(lo), "f"(hi)); return r;
}
__device__ __forceinline__ void unpack2(ull v, float& lo, float& hi) {
    asm("mov.b64 {%0, %1}, %2;" : "=f"(lo), "=f"(hi) : "l"(v));
}
__device__ __forceinline__ void fma2(ull& d, ull a, ull b) {
    asm("fma.rn.f32x2 %0, %1, %2, %0;" : "+l"(d) : "l"(a), "l"(b));
}
__device__ __forceinline__ u32 f2tf32(float f) {
    u32 r; asm("cvt.rna.tf32.f32 %0, %1;" : "=r"(r) : "f"(f)); return r;
}
__device__ __forceinline__ u32 smem_u32(const void* p) {
    u32 a; asm("{ .reg .u64 t; cvta.to.shared.u64 t, %1; cvt.u32.u64 %0, t; }" : "=r"(a) : "l"(p));
    return a;
}
__device__ __forceinline__ void cp16(u32 dst, const void* src) {
    asm volatile("cp.async.ca.shared.global [%0], [%1], 16;" :: "r"(dst), "l"(src));
}
#define CP_COMMIT() asm volatile("cp.async.commit_group;" ::: "memory")
#define CP_WAIT(N)  asm volatile("cp.async.wait_group %0;" :: "n"(N) : "memory")

__device__ __forceinline__ void mma_tf32(float* c, const u32* a, const u32* b) {
    asm volatile("mma.sync.aligned.m16n8k8.row.col.f32.tf32.tf32.f32 "
                 "{%0,%1,%2,%3}, {%4,%5,%6,%7}, {%8,%9}, {%0,%1,%2,%3};"
                 : "+f"(c[0]), "+f"(c[1]), "+f"(c[2]), "+f"(c[3])
                 : "r"(a[0]), "r"(a[1]), "r"(a[2]), "r"(a[3]),
                   "r"(b[0]), "r"(b[1]));
}

// ======================= scratch =======================
__device__ __align__(16) float g_p1[8 * 256 * 66 * 66];        // padded conv1 input, tf32-rounded
__device__ __align__(16) float g_out1[8 * 256 * 64 * 64];      // conv1 output (after lrelu, fp32)
__device__ __align__(16) float g_up_pad[8 * 256 * 130 * 130];  // padded upsampled, tf32-rounded
__device__ __align__(16) float g_s64[8 * 128 * 64 * 64];       // 1x1 skip conv at 64x64 (fp32)
__device__ __align__(16) u32   g_wB1[2 * 72 * 4096];           // conv1 wts tf32 [cot][chunk][k=32][co=128]
__device__ __align__(16) u32   g_wB2[72 * 4096];               // conv2 wts tf32 [chunk][k=32][co=128]
__device__ __align__(16) float g_wskT[256 * 128];              // skip weights [ci][co], scaled

// ======================= weight prep =======================
__global__ void k_wt1(const float* __restrict__ w) {
    int idx = blockIdx.x * 256 + threadIdx.x;        // 2*72*32*128 = 589824
    if (idx >= 589824) return;
    int co_l  = idx & 127;
    int k_l   = (idx >> 7) & 31;
    int chunk = idx >> 12;                            // 0..143
    int cot = chunk / 72, i = chunk % 72;
    int koff = i >> 3, cic = i & 7;
    int co = cot * 128 + co_l;
    int ci = cic * 32 + k_l;
    g_wB1[idx] = f2tf32(w[(co * 256 + ci) * 9 + koff] * (1.0f / 48.0f));
}
__global__ void k_wt2(const float* __restrict__ w) {
    int idx = blockIdx.x * 256 + threadIdx.x;        // 72*32*128 = 294912
    if (idx >= 294912) return;
    int co_l = idx & 127;
    int k_l  = (idx >> 7) & 31;
    int i    = idx >> 12;                             // 0..71
    int koff = i >> 3, cic = i & 7;
    int ci = cic * 32 + k_l;
    g_wB2[idx] = f2tf32(w[(co_l * 256 + ci) * 9 + koff] * (1.0f / 48.0f));
}
__global__ void k_wts(const float* __restrict__ w) {
    int idx = blockIdx.x * 256 + threadIdx.x;
    if (idx >= 256 * 128) return;
    int co = idx & 127; int ci = idx >> 7;
    g_wskT[idx] = w[co * 256 + ci] * (1.0f / 16.0f);
}

// ======================= pad x into g_p1 (tf32-rounded) =======================
__global__ void k_pad1(const float* __restrict__ x) {
    int idx = blockIdx.x * 256 + threadIdx.x;        // 8*256*64*64
    int c = idx & 63, r = (idx >> 6) & 63, nc = idx >> 12;
    g_p1[(size_t)nc * 4356 + (r + 1) * 66 + (c + 1)] = __uint_as_float(f2tf32(x[idx]));
}

// ======================= mma.sync tf32 implicit-GEMM conv (3x3, pad 1) =================
// A: LDG register-prefetch (1 iter ahead) + STS, 2 SMEM stages.
// B: 16B cp.async, 3-stage ring, issued 2 iters ahead.
// smem = (2 + 3) * 4352 u32 = 87040 B dynamic.
// CONV=1: in=g_p1 (66x66 pad), out 64x64, M-tile = 2 rows x 64 cols, cot {0,1} -> g_out1
// CONV=2: in=g_up_pad (130x130 pad), out 128x128, M-tile = 1 row x 128 cols -> d_out (+ fused skip)
template <int CONV>
__global__ void __launch_bounds__(256, 2) k_conv_mma(const float* __restrict__ bias,
                                                     float* __restrict__ dout) {
    constexpr int PW  = (CONV == 1) ? 66 : 130;
    constexpr int PSZ = PW * PW;
    constexpr int OW  = (CONV == 1) ? 64 : 128;
    constexpr int ROWS = 128 / OW;
    constexpr int TILE = 32 * 136;                   // 4352 u32 per stage

    extern __shared__ __align__(16) u32 dynsmem[];
    const u32 sbase = smem_u32(dynsmem);

    const int tile = blockIdx.x;
    const int cot  = blockIdx.y;
    const int n    = blockIdx.z;
    const int tid  = threadIdx.x;
    const int wid  = tid >> 5;
    const int lane = tid & 31;
    const int warp_m = wid >> 1;       // 0..3
    const int warp_n = wid & 1;        // 0..1
    const int lg = lane >> 2;          // 0..7
    const int lt = lane & 3;           // 0..3

    const float* in = (CONV == 1) ? g_p1 : g_up_pad;
    const u32* wB = ((CONV == 1) ? g_wB1 + cot * 72 * 4096 : g_wB2);

    const int r0 = tile * ROWS;

    // A mapping: thread = one px of the 128-px M-tile, 16 ci per load (stride 2*PSZ)
    const int px = tid & 127;
    const int rl = (CONV == 1) ? (px >> 6) : 0;
    const int c  = px & (OW - 1);
    const int cihalf = tid >> 7;                 // 0..1
    const float* a_base = in + ((size_t)(n * 256 + cihalf)) * PSZ
                             + (size_t)(r0 + rl) * PW + c;

    // B cp.async issue (tile chunk i -> stage st)
    auto issueB = [&](int i, int st) {
        const u32* src = wB + i * 4096;
        u32 dstb = sbase + (u32)((2 + st) * TILE * 4);
#pragma unroll
        for (int p = 0; p < 4; p++) {
            int lin = (p * 256 + tid) << 2;          // u32 index, mult of 4
            int row = lin >> 7, col = lin & 127;
            cp16(dstb + (u32)((row * 136 + col) << 2), src + lin);
        }
        CP_COMMIT();
    };
    // A LDG into regs
    float rA[16];
    auto ldgA = [&](int i) {
        const int koff = i >> 3, cic = i & 7;
        const int ky = koff / 3, kx = koff - ky * 3;
        const float* src = a_base + (size_t)(cic * 32) * PSZ + ky * PW + kx;
#pragma unroll
        for (int j = 0; j < 16; j++) rA[j] = __ldg(src + (size_t)(2 * j) * PSZ);
    };
    auto stsA = [&](int st) {
        u32* sp = dynsmem + st * TILE + cihalf * 136 + px;
#pragma unroll
        for (int j = 0; j < 16; j++) sp[2 * j * 136] = __float_as_uint(rA[j]);
    };

    float acc[2][8][4];
#pragma unroll
    for (int mt = 0; mt < 2; mt++)
#pragma unroll
        for (int nt = 0; nt < 8; nt++)
#pragma unroll
            for (int q = 0; q < 4; q++) acc[mt][nt][q] = 0.0f;

    // ---- prologue ----
    issueB(0, 0);
    issueB(1, 1);
    ldgA(0); stsA(0);
    ldgA(1);
    CP_WAIT(1);
    __syncthreads();

    int stB = 0;                                     // B stage of current tile
    for (int i = 0; i < 72; i++) {
        const int stA = i & 1;
        int stB2 = stB + 2; if (stB2 >= 3) stB2 -= 3;
        if (i + 2 < 72) issueB(i + 2, stB2);

        const u32* sA = dynsmem + stA * TILE;
        const u32* sB = dynsmem + (2 + stB) * TILE;
#pragma unroll
        for (int ks = 0; ks < 4; ks++) {
            const int kc = ks * 8 + lt;
            const int rb = warp_m * 32 + lg;
            u32 a[2][4];
#pragma unroll
            for (int mt = 0; mt < 2; mt++) {
                a[mt][0] = sA[kc * 136 + rb + mt * 16];
                a[mt][1] = sA[kc * 136 + rb + mt * 16 + 8];
                a[mt][2] = sA[(kc + 4) * 136 + rb + mt * 16];
                a[mt][3] = sA[(kc + 4) * 136 + rb + mt * 16 + 8];
            }
            const int nb = warp_n * 64 + lg;
            u32 b[8][2];
#pragma unroll
            for (int nt = 0; nt < 8; nt++) {
                b[nt][0] = sB[kc * 136 + nb + nt * 8];
                b[nt][1] = sB[(kc + 4) * 136 + nb + nt * 8];
            }
#pragma unroll
            for (int mt = 0; mt < 2; mt++)
#pragma unroll
                for (int nt = 0; nt < 8; nt++)
                    mma_tf32(acc[mt][nt], a[mt], b[nt]);
        }

        if (i + 1 < 72) {
            stsA(stA ^ 1);                           // A(i+1) regs -> other stage
            if (i + 2 < 72) { ldgA(i + 2); CP_WAIT(1); }
            else            { CP_WAIT(0); }
            __syncthreads();                         // publish A(i+1) STS + B(i+1) cp.async
        }
        if (++stB == 3) stB = 0;
    }

    // ---- epilogue ----
    if (CONV == 1) {
#pragma unroll
        for (int mt = 0; mt < 2; mt++) {
            const int p0 = warp_m * 32 + mt * 16 + lg;
            const int p1 = p0 + 8;
            const int or0 = r0 + (p0 >> 6), oc0 = p0 & 63;
            const int or1 = r0 + (p1 >> 6), oc1 = p1 & 63;
#pragma unroll
            for (int nt = 0; nt < 8; nt++) {
                const int co = cot * 128 + warp_n * 64 + nt * 8 + lt * 2;
                const float bv0 = bias[co], bv1 = bias[co + 1];
                float v00 = acc[mt][nt][0] + bv0;  v00 = (v00 >= 0.0f ? v00 : 0.2f * v00) * SQRT2F;
                float v01 = acc[mt][nt][1] + bv1;  v01 = (v01 >= 0.0f ? v01 : 0.2f * v01) * SQRT2F;
                float v10 = acc[mt][nt][2] + bv0;  v10 = (v10 >= 0.0f ? v10 : 0.2f * v10) * SQRT2F;
                float v11 = acc[mt][nt][3] + bv1;  v11 = (v11 >= 0.0f ? v11 : 0.2f * v11) * SQRT2F;
                g_out1[((size_t)(n * 256 + co)     << 12) + (or0 << 6) + oc0] = v00;
                g_out1[((size_t)(n * 256 + co + 1) << 12) + (or0 << 6) + oc0] = v01;
                g_out1[((size_t)(n * 256 + co)     << 12) + (or1 << 6) + oc1] = v10;
                g_out1[((size_t)(n * 256 + co + 1) << 12) + (or1 << 6) + oc1] = v11;
            }
        }
    } else {
        // fused: out = (conv2_act + bilinear_up(g_s64)) / sqrt(2); row u = r0 fixed.
        const int u = r0;
        int rr0, rr1; float wr0, wr1;
        { int iu = u >> 1;
          if (u & 1) { rr0 = iu; rr1 = min(iu + 1, 63); wr0 = 0.75f; wr1 = 0.25f; }
          else       { rr0 = max(iu - 1, 0); rr1 = iu;  wr0 = 0.25f; wr1 = 0.75f; } }
#pragma unroll
        for (int mt = 0; mt < 2; mt++) {
#pragma unroll
            for (int half = 0; half < 2; half++) {
                const int p  = warp_m * 32 + mt * 16 + half * 8 + lg;  // output col v
                int cc0, cc1; float wc0, wc1;
                { int jv = p >> 1;
                  if (p & 1) { cc0 = jv; cc1 = min(jv + 1, 63); wc0 = 0.75f; wc1 = 0.25f; }
                  else       { cc0 = max(jv - 1, 0); cc1 = jv;  wc0 = 0.25f; wc1 = 0.75f; } }
                const int i00 = (rr0 << 6) + cc0, i01 = (rr0 << 6) + cc1;
                const int i10 = (rr1 << 6) + cc0, i11 = (rr1 << 6) + cc1;
#pragma unroll
                for (int nt = 0; nt < 8; nt++) {
                    const int co = warp_n * 64 + nt * 8 + lt * 2;
                    const float bv0 = bias[co], bv1 = bias[co + 1];
                    float va = acc[mt][nt][half * 2 + 0] + bv0;
                    va = (va >= 0.0f ? va : 0.2f * va) * SQRT2F;
                    float vb = acc[mt][nt][half * 2 + 1] + bv1;
                    vb = (vb >= 0.0f ? vb : 0.2f * vb) * SQRT2F;
                    const float* s0 = g_s64 + ((size_t)(n * 128 + co) << 12);
                    const float* s1 = s0 + 4096;
                    float sk0 = wr0 * (wc0 * s0[i00] + wc1 * s0[i01])
                              + wr1 * (wc0 * s0[i10] + wc1 * s0[i11]);
                    float sk1 = wr0 * (wc0 * s1[i00] + wc1 * s1[i01])
                              + wr1 * (wc0 * s1[i10] + wc1 * s1[i11]);
                    dout[((size_t)(n * 128 + co)     << 14) + (u << 7) + p] = (va + sk0) * INVSQRT2F;
                    dout[((size_t)(n * 128 + co + 1) << 14) + (u << 7) + p] = (vb + sk1) * INVSQRT2F;
                }
            }
        }
    }
}

// ======================= bilinear 2x upsample (half-pixel, edge clamp) =================
__global__ void k_up256() {   // g_out1[.,.,64,64] -> g_up_pad interior [130x130], tf32-rounded
    int idx = blockIdx.x * 256 + threadIdx.x;
    int v = idx & 127, u = (idx >> 7) & 127, nc = idx >> 14;
    int i = u >> 1, j = v >> 1;
    int r0, r1, c0, c1; float wr0, wr1, wc0, wc1;
    if (u & 1) { r0 = i; r1 = min(i + 1, 63); wr0 = 0.75f; wr1 = 0.25f; }
    else       { r0 = max(i - 1, 0); r1 = i;  wr0 = 0.25f; wr1 = 0.75f; }
    if (v & 1) { c0 = j; c1 = min(j + 1, 63); wc0 = 0.75f; wc1 = 0.25f; }
    else       { c0 = max(j - 1, 0); c1 = j;  wc0 = 0.25f; wc1 = 0.75f; }
    const float* b = g_out1 + ((size_t)nc << 12);
    float val = wr0 * (wc0 * b[(r0 << 6) + c0] + wc1 * b[(r0 << 6) + c1])
              + wr1 * (wc0 * b[(r1 << 6) + c0] + wc1 * b[(r1 << 6) + c1]);
    g_up_pad[(size_t)nc * 16900 + (u + 1) * 130 + (v + 1)] = __uint_as_float(f2tf32(val));
}

// ======================= skip 1x1 conv at 64x64 (256->128), fp32 f32x2 =================
__global__ void __launch_bounds__(256) k_skip(const float* __restrict__ x) {
    const int n = blockIdx.z, cot = blockIdx.y;
    const int px0 = blockIdx.x * 64;
    const int tid = threadIdx.x;
    const int co_sub = tid >> 4, pxg = tid & 15;
    const int cobase = co_sub * 4, pxb = pxg * 4;
    __shared__ __align__(16) float s_x[16][64];
    __shared__ __align__(16) float s_w[16][64];
    ull acc[2][4];
#pragma unroll
    for (int p = 0; p < 2; p++)
#pragma unroll
        for (int j = 0; j < 4; j++) acc[p][j] = 0ull;

    for (int ci0 = 0; ci0 < 256; ci0 += 16) {
        __syncthreads();
        for (int i = tid; i < 1024; i += 256) {
            int ci_l = i >> 6, p = i & 63;
            s_x[ci_l][p] = x[((n * 256 + ci0 + ci_l) << 12) + px0 + p];
            s_w[ci_l][p] = g_wskT[(ci0 + ci_l) * 128 + cot * 64 + p];
        }
        __syncthreads();
#pragma unroll 4
        for (int ci = 0; ci < 16; ci++) {
            ull w0 = *(const ull*)&s_w[ci][cobase];
            ull w1 = *(const ull*)&s_w[ci][cobase + 2];
#pragma unroll
            for (int j = 0; j < 4; j++) {
                float v = s_x[ci][pxb + j];
                ull vb = pack2(v, v);
                fma2(acc[0][j], vb, w0);
                fma2(acc[1][j], vb, w1);
            }
        }
    }
#pragma unroll
    for (int p = 0; p < 2; p++) {
        int co = cot * 64 + cobase + 2 * p;
#pragma unroll
        for (int j = 0; j < 4; j++) {
            float lo, hi; unpack2(acc[p][j], lo, hi);
            g_s64[((n * 128 + co)     << 12) + px0 + pxb + j] = lo;
            g_s64[((n * 128 + co + 1) << 12) + px0 + pxb + j] = hi;
        }
    }
}

// ======================= launch =======================
extern "C" void kernel_launch(void* const* d_in, const int* in_sizes, int n_in,
                              void* d_out, int out_size) {
    const float* x   = (const float*)d_in[0];
    const float* w1  = (const float*)d_in[1];
    const float* b1  = (const float*)d_in[2];
    const float* w2  = (const float*)d_in[3];
    const float* b2  = (const float*)d_in[4];
    const float* wsk = (const float*)d_in[5];
    float* out = (float*)d_out;

    static const int SMEM_CONV = 5 * 32 * 136 * 4;   // 87040 B
    cudaFuncSetAttribute(k_conv_mma<1>, cudaFuncAttributeMaxDynamicSharedMemorySize, SMEM_CONV);
    cudaFuncSetAttribute(k_conv_mma<2>, cudaFuncAttributeMaxDynamicSharedMemorySize, SMEM_CONV);

    k_wt1<<<2304, 256>>>(w1);
    k_wt2<<<1152, 256>>>(w2);
    k_wts<<<128, 256>>>(wsk);
    k_pad1<<<32768, 256>>>(x);

    k_conv_mma<1><<<dim3(32, 2, 8), 256, SMEM_CONV>>>(b1, nullptr);
    k_up256<<<131072, 256>>>();                            // -> padded g_up_pad (tf32)
    k_skip<<<dim3(64, 2, 8), 256>>>(x);
    k_conv_mma<2><<<dim3(128, 1, 8), 256, SMEM_CONV>>>(b2, out);  // conv2 + fused skip
}